// round 1
// baseline (speedup 1.0000x reference)
#include <cuda_runtime.h>
#include <cstdint>

#define D1 256
#define D2 128
#define K_DIM 256

static const int MAX_N = 100000;
static const int MAX_E = 1600000;

// Scratch (device globals — no allocation allowed)
__device__ float g_y1[MAX_N * D1];
__device__ float g_z1[MAX_N * D1];
__device__ float g_agg1[MAX_N * D1];
__device__ float g_h[MAX_N * D1];
__device__ float g_y2[MAX_N * D2];
__device__ float g_z2[MAX_N * D2];
__device__ float g_agg2[MAX_N * D2];
__device__ float g_deg[MAX_N];

// ---------------------------------------------------------------------------
// degree: one float atomic per edge
// ---------------------------------------------------------------------------
__global__ void deg_kernel(const int* __restrict__ dst, float* __restrict__ deg, int E) {
    int i = blockIdx.x * blockDim.x + threadIdx.x;
    if (i < E) atomicAdd(&deg[dst[i]], 1.0f);
}

// ---------------------------------------------------------------------------
// SGEMM: C[M,Ncols] = A[M,K] @ W[Ncols,K]^T (+ bias). K fixed at 256.
// 128x128 tile, BK=8, 256 threads, 8x8 register tile.
// ---------------------------------------------------------------------------
#define SMEM_LD 132   // padded row stride (132*4B = 528B, 16B aligned, conflict-free)

__global__ __launch_bounds__(256, 2)
void sgemm_tn(const float* __restrict__ A, const float* __restrict__ W,
              const float* __restrict__ bias, float* __restrict__ C,
              int M, int Ncols) {
    __shared__ float As[8 * SMEM_LD];
    __shared__ float Bs[8 * SMEM_LD];

    const int tid = threadIdx.x;
    const int tx = tid & 15;        // 0..15  (n direction)
    const int ty = tid >> 4;        // 0..15  (m direction)
    const int m0 = blockIdx.y * 128;
    const int n0 = blockIdx.x * 128;

    float acc[8][8];
#pragma unroll
    for (int i = 0; i < 8; i++)
#pragma unroll
        for (int j = 0; j < 8; j++) acc[i][j] = 0.0f;

    const int lrow = tid >> 1;          // 0..127
    const int lcg  = (tid & 1) * 4;     // 0 or 4

    for (int k0 = 0; k0 < K_DIM; k0 += 8) {
        // load A tile (transposed into smem: As[k][m])
        float4 av = make_float4(0.f, 0.f, 0.f, 0.f);
        int gm = m0 + lrow;
        if (gm < M) av = *(const float4*)(A + (size_t)gm * K_DIM + k0 + lcg);
        As[(lcg + 0) * SMEM_LD + lrow] = av.x;
        As[(lcg + 1) * SMEM_LD + lrow] = av.y;
        As[(lcg + 2) * SMEM_LD + lrow] = av.z;
        As[(lcg + 3) * SMEM_LD + lrow] = av.w;

        // load W tile (Bs[k][n])
        float4 wv = make_float4(0.f, 0.f, 0.f, 0.f);
        int gn = n0 + lrow;
        if (gn < Ncols) wv = *(const float4*)(W + (size_t)gn * K_DIM + k0 + lcg);
        Bs[(lcg + 0) * SMEM_LD + lrow] = wv.x;
        Bs[(lcg + 1) * SMEM_LD + lrow] = wv.y;
        Bs[(lcg + 2) * SMEM_LD + lrow] = wv.z;
        Bs[(lcg + 3) * SMEM_LD + lrow] = wv.w;

        __syncthreads();

#pragma unroll
        for (int kk = 0; kk < 8; kk++) {
            float a[8], b[8];
            const float4* ap = (const float4*)(As + kk * SMEM_LD + ty * 8);
            const float4* bp = (const float4*)(Bs + kk * SMEM_LD + tx * 8);
            float4 a0 = ap[0], a1 = ap[1];
            float4 b0 = bp[0], b1 = bp[1];
            a[0] = a0.x; a[1] = a0.y; a[2] = a0.z; a[3] = a0.w;
            a[4] = a1.x; a[5] = a1.y; a[6] = a1.z; a[7] = a1.w;
            b[0] = b0.x; b[1] = b0.y; b[2] = b0.z; b[3] = b0.w;
            b[4] = b1.x; b[5] = b1.y; b[6] = b1.z; b[7] = b1.w;
#pragma unroll
            for (int i = 0; i < 8; i++)
#pragma unroll
                for (int j = 0; j < 8; j++)
                    acc[i][j] += a[i] * b[j];
        }
        __syncthreads();
    }

    // epilogue
#pragma unroll
    for (int i = 0; i < 8; i++) {
        int gm = m0 + ty * 8 + i;
        if (gm >= M) continue;
#pragma unroll
        for (int j = 0; j < 8; j += 4) {
            int gn = n0 + tx * 8 + j;
            float4 v = make_float4(acc[i][j], acc[i][j + 1], acc[i][j + 2], acc[i][j + 3]);
            if (bias) {
                v.x += bias[gn]; v.y += bias[gn + 1];
                v.z += bias[gn + 2]; v.w += bias[gn + 3];
            }
            *(float4*)(C + (size_t)gm * Ncols + gn) = v;
        }
    }
}

// ---------------------------------------------------------------------------
// Edge scatter: agg[dst] += feat[src], one warp per edge, vector f32 red.
// ---------------------------------------------------------------------------
__device__ __forceinline__ void red_add_v4(float* p, float4 v) {
    asm volatile("red.global.add.v4.f32 [%0], {%1, %2, %3, %4};"
                 :: "l"(p), "f"(v.x), "f"(v.y), "f"(v.z), "f"(v.w)
                 : "memory");
}

template <int D>
__global__ void scatter_add_kernel(const float* __restrict__ feat,
                                   const int* __restrict__ src,
                                   const int* __restrict__ dst,
                                   float* __restrict__ agg, int E) {
    int warp = (blockIdx.x * blockDim.x + threadIdx.x) >> 5;
    int lane = threadIdx.x & 31;
    if (warp >= E) return;
    int s = src[warp];
    int d = dst[warp];
    const float4* in = (const float4*)(feat + (size_t)s * D);
    float* outp = agg + (size_t)d * D;
#pragma unroll
    for (int i = 0; i < D / 128; i++) {
        int idx = lane + i * 32;
        float4 v = in[idx];
        red_add_v4(outp + idx * 4, v);
    }
}

// ---------------------------------------------------------------------------
// Combine: out = (relu?)(agg / max(deg,1) + z)
// ---------------------------------------------------------------------------
template <bool RELU, int DQ>  // DQ = D/4
__global__ void combine_kernel(const float* __restrict__ agg,
                               const float* __restrict__ z,
                               const float* __restrict__ deg,
                               float* __restrict__ out, int total4) {
    int i = blockIdx.x * blockDim.x + threadIdx.x;
    if (i >= total4) return;
    int row = i / DQ;
    float sc = 1.0f / fmaxf(deg[row], 1.0f);
    float4 a = ((const float4*)agg)[i];
    float4 zz = ((const float4*)z)[i];
    float4 r;
    r.x = a.x * sc + zz.x;
    r.y = a.y * sc + zz.y;
    r.z = a.z * sc + zz.z;
    r.w = a.w * sc + zz.w;
    if (RELU) {
        r.x = fmaxf(r.x, 0.f); r.y = fmaxf(r.y, 0.f);
        r.z = fmaxf(r.z, 0.f); r.w = fmaxf(r.w, 0.f);
    }
    ((float4*)out)[i] = r;
}

// ---------------------------------------------------------------------------
// Launch
// ---------------------------------------------------------------------------
extern "C" void kernel_launch(void* const* d_in, const int* in_sizes, int n_in,
                              void* d_out, int out_size) {
    const float* x    = (const float*)d_in[0];
    const int* eidx   = (const int*)d_in[1];
    const float* W1l  = (const float*)d_in[2];
    const float* b1   = (const float*)d_in[3];
    const float* W1r  = (const float*)d_in[4];
    const float* W2l  = (const float*)d_in[5];
    const float* b2   = (const float*)d_in[6];
    const float* W2r  = (const float*)d_in[7];
    float* out = (float*)d_out;

    const int N = in_sizes[0] / D1;
    const int E = in_sizes[1] / 2;
    const int* src = eidx;
    const int* dst = eidx + E;

    float *y1, *z1, *agg1, *h, *y2, *z2, *agg2, *deg;
    cudaGetSymbolAddress((void**)&y1,   g_y1);
    cudaGetSymbolAddress((void**)&z1,   g_z1);
    cudaGetSymbolAddress((void**)&agg1, g_agg1);
    cudaGetSymbolAddress((void**)&h,    g_h);
    cudaGetSymbolAddress((void**)&y2,   g_y2);
    cudaGetSymbolAddress((void**)&z2,   g_z2);
    cudaGetSymbolAddress((void**)&agg2, g_agg2);
    cudaGetSymbolAddress((void**)&deg,  g_deg);

    cudaMemsetAsync(agg1, 0, (size_t)N * D1 * sizeof(float));
    cudaMemsetAsync(agg2, 0, (size_t)N * D2 * sizeof(float));
    cudaMemsetAsync(deg,  0, (size_t)N * sizeof(float));

    deg_kernel<<<(E + 255) / 256, 256>>>(dst, deg, E);

    dim3 g1(D1 / 128, (N + 127) / 128);
    sgemm_tn<<<g1, 256>>>(x, W1l, nullptr, y1, N, D1);
    sgemm_tn<<<g1, 256>>>(x, W1r, b1,      z1, N, D1);

    int scatterBlocks = (E + 7) / 8;  // 8 warps/block, one warp per edge
    scatter_add_kernel<D1><<<scatterBlocks, 256>>>(y1, src, dst, agg1, E);

    int t1 = N * (D1 / 4);
    combine_kernel<true, D1 / 4><<<(t1 + 255) / 256, 256>>>(agg1, z1, deg, h, t1);

    dim3 g2(D2 / 128, (N + 127) / 128);
    sgemm_tn<<<g2, 256>>>(h, W2l, nullptr, y2, N, D2);
    sgemm_tn<<<g2, 256>>>(h, W2r, b2,      z2, N, D2);

    scatter_add_kernel<D2><<<scatterBlocks, 256>>>(y2, src, dst, agg2, E);

    int t2 = N * (D2 / 4);
    combine_kernel<false, D2 / 4><<<(t2 + 255) / 256, 256>>>(agg2, z2, deg, out, t2);
}

// round 3
// speedup vs baseline: 1.4433x; 1.4433x over previous
#include <cuda_runtime.h>
#include <cuda_bf16.h>
#include <cstdint>

#define D1 256
#define D2 128
#define K_DIM 256

static const int MAX_N = 100000;
static const int MAX_E = 1600000;

// fp32 scratch
__device__ float g_y1[MAX_N * D1];
__device__ float g_z1[MAX_N * D1];
__device__ float g_agg1[MAX_N * D1];
__device__ float g_y2[MAX_N * D2];
__device__ float g_z2[MAX_N * D2];
__device__ float g_agg2[MAX_N * D2];
__device__ float g_deg[MAX_N];
// bf16 split scratch
__device__ __nv_bfloat16 g_xhi[MAX_N * D1];
__device__ __nv_bfloat16 g_xlo[MAX_N * D1];
__device__ __nv_bfloat16 g_hhi[MAX_N * D1];
__device__ __nv_bfloat16 g_hlo[MAX_N * D1];
// weight splits: [w1l_hi, w1l_lo, w1r_hi, w1r_lo] (64K each) then
// [w2l_hi, w2l_lo, w2r_hi, w2r_lo] (32K each)
__device__ __nv_bfloat16 g_w[4 * 65536 + 4 * 32768];

// ---------------------------------------------------------------------------
__device__ __forceinline__ uint32_t smem_to_u32(const void* p) {
    uint32_t a;
    asm("{ .reg .u64 t; cvta.to.shared.u64 t, %1; cvt.u32.u64 %0, t; }"
        : "=r"(a) : "l"(p));
    return a;
}

__device__ __forceinline__ void cp_async16(uint32_t saddr, const void* gaddr, uint32_t n) {
    asm volatile("cp.async.cg.shared.global [%0], [%1], 16, %2;"
                 :: "r"(saddr), "l"(gaddr), "r"(n) : "memory");
}

__device__ __forceinline__ void mma_bf16(float* c, const uint32_t* a, const uint32_t* b) {
    asm volatile(
        "mma.sync.aligned.m16n8k16.row.col.f32.bf16.bf16.f32 "
        "{%0,%1,%2,%3}, {%4,%5,%6,%7}, {%8,%9}, {%0,%1,%2,%3};"
        : "+f"(c[0]), "+f"(c[1]), "+f"(c[2]), "+f"(c[3])
        : "r"(a[0]), "r"(a[1]), "r"(a[2]), "r"(a[3]), "r"(b[0]), "r"(b[1]));
}

// ---------------------------------------------------------------------------
// bf16x3 dual GEMM:
//   Cl = A @ Wl^T            (no bias)
//   Cr = A @ Wr^T + bias_r
// A is M x 256 fp32 given as (hi, lo) bf16 pair; W is NCOLS x 256 as (hi, lo).
// Effective K = 768: blocks (A,B) = (hi,hi), (lo,hi), (hi,lo).
// ---------------------------------------------------------------------------
template <int NCOLS>
__global__ __launch_bounds__(256, 2)
void gemm_bf16x3(const __nv_bfloat16* __restrict__ Ahi,
                 const __nv_bfloat16* __restrict__ Alo,
                 const __nv_bfloat16* __restrict__ Wlhi,
                 const __nv_bfloat16* __restrict__ Wllo,
                 const __nv_bfloat16* __restrict__ Wrhi,
                 const __nv_bfloat16* __restrict__ Wrlo,
                 const float* __restrict__ bias_r,
                 float* __restrict__ Cl, float* __restrict__ Cr, int M) {
    constexpr int NB_HALF = NCOLS / 128;
    constexpr int ROWB = 80;             // padded smem row stride (bytes)
    constexpr int TILE = 128 * ROWB;     // 10240 B
    constexpr int KC = 24;               // 768 / 32
    __shared__ char smem[4 * TILE];      // 2 stages x (A,B)

    const int tid = threadIdx.x;
    const int wid = tid >> 5, lane = tid & 31;
    const int g = lane >> 2, t = lane & 3;
    const int half = (int)blockIdx.x / NB_HALF;
    const int n0 = ((int)blockIdx.x % NB_HALF) * 128;
    const int m0 = (int)blockIdx.y * 128;
    const __nv_bfloat16* Whi = half ? Wrhi : Wlhi;
    const __nv_bfloat16* Wlo = half ? Wrlo : Wllo;
    float* C = half ? Cr : Cl;
    const float* bias = half ? bias_r : nullptr;

    const int wr = wid >> 2;    // 0..1 -> m offset wr*64
    const int wc = wid & 3;     // 0..3 -> n offset wc*32

    float acc[4][4][4];
#pragma unroll
    for (int i = 0; i < 4; i++)
#pragma unroll
        for (int j = 0; j < 4; j++)
#pragma unroll
            for (int k = 0; k < 4; k++) acc[i][j][k] = 0.0f;

    const uint32_t sbase = smem_to_u32(smem);

    // loader: 512 16B-chunks per tile; thread covers 2 chunks of A + 2 of B
    const int lrow0 = tid >> 1;                // rows tid>>1 and (tid+256)>>1
    const int lc0 = (tid & 1) * 2;             // chunk cols {0,1} or {2,3}

    auto issue = [&](int kc, int stage) {
        int blk = kc >> 3;
        int kin = (kc & 7) * 32;
        const __nv_bfloat16* Ab = (blk == 1) ? Alo : Ahi;
        const __nv_bfloat16* Bb = (blk == 2) ? Wlo : Whi;
        uint32_t sA = sbase + (uint32_t)stage * 2 * TILE;
        uint32_t sB = sA + TILE;
#pragma unroll
        for (int i = 0; i < 2; i++) {
            int row = lrow0 + i * 128;   // wraps: i=0 rows 0..127? no: tid>>1 in 0..127, +128 invalid
            (void)row;
        }
        // A: chunk id = tid .. tid+256 ; id>>2 = row (0..127), id&3 = col chunk
#pragma unroll
        for (int i = 0; i < 2; i++) {
            int id = tid + i * 256;
            int row = id >> 2, c = id & 3;
            int gm = m0 + row;
            uint32_t p = (gm < M) ? 16u : 0u;
            cp_async16(sA + row * ROWB + c * 16,
                       Ab + (size_t)gm * K_DIM + kin + c * 8, p);
            cp_async16(sB + row * ROWB + c * 16,
                       Bb + (size_t)(n0 + row) * K_DIM + kin + c * 8, 16u);
        }
        asm volatile("cp.async.commit_group;" ::: "memory");
    };

    auto compute = [&](int stage) {
        const char* sA = smem + (size_t)stage * 2 * TILE;
        const char* sB = sA + TILE;
#pragma unroll
        for (int s = 0; s < 2; s++) {
            const int kb = s * 32;  // byte offset of k16 step (16 bf16 = 32B)
            uint32_t a[4][4], b[4][2];
#pragma unroll
            for (int mi = 0; mi < 4; mi++) {
                int r = wr * 64 + mi * 16 + g;
                const char* base = sA + kb + t * 4;
                a[mi][0] = *(const uint32_t*)(base + (size_t)r * ROWB);
                a[mi][1] = *(const uint32_t*)(base + (size_t)(r + 8) * ROWB);
                a[mi][2] = *(const uint32_t*)(base + (size_t)r * ROWB + 16);
                a[mi][3] = *(const uint32_t*)(base + (size_t)(r + 8) * ROWB + 16);
            }
#pragma unroll
            for (int ni = 0; ni < 4; ni++) {
                int n = wc * 32 + ni * 8 + g;
                const char* base = sB + kb + t * 4 + (size_t)n * ROWB;
                b[ni][0] = *(const uint32_t*)(base);
                b[ni][1] = *(const uint32_t*)(base + 16);
            }
#pragma unroll
            for (int mi = 0; mi < 4; mi++)
#pragma unroll
                for (int ni = 0; ni < 4; ni++)
                    mma_bf16(acc[mi][ni], a[mi], b[ni]);
        }
    };

    issue(0, 0);
    for (int kc = 0; kc < KC; kc++) {
        if (kc + 1 < KC) {
            issue(kc + 1, (kc + 1) & 1);
            asm volatile("cp.async.wait_group 1;" ::: "memory");
        } else {
            asm volatile("cp.async.wait_group 0;" ::: "memory");
        }
        __syncthreads();
        compute(kc & 1);
        __syncthreads();
    }

    // epilogue
#pragma unroll
    for (int mi = 0; mi < 4; mi++) {
        int r0 = m0 + wr * 64 + mi * 16 + g;
#pragma unroll
        for (int ni = 0; ni < 4; ni++) {
            int col = n0 + wc * 32 + ni * 8 + t * 2;
            float bx = 0.f, by = 0.f;
            if (bias) { bx = __ldg(bias + col); by = __ldg(bias + col + 1); }
            if (r0 < M)
                *(float2*)(C + (size_t)r0 * NCOLS + col) =
                    make_float2(acc[mi][ni][0] + bx, acc[mi][ni][1] + by);
            if (r0 + 8 < M)
                *(float2*)(C + (size_t)(r0 + 8) * NCOLS + col) =
                    make_float2(acc[mi][ni][2] + bx, acc[mi][ni][3] + by);
        }
    }
}

// ---------------------------------------------------------------------------
// fp32 -> (bf16 hi, bf16 lo) split
// ---------------------------------------------------------------------------
__device__ __forceinline__ void split1(float v, __nv_bfloat16& h, __nv_bfloat16& l) {
    h = __float2bfloat16(v);
    l = __float2bfloat16(v - __bfloat162float(h));
}

__global__ void split_kernel(const float* __restrict__ in,
                             __nv_bfloat16* __restrict__ hi,
                             __nv_bfloat16* __restrict__ lo, int n4) {
    int i = blockIdx.x * blockDim.x + threadIdx.x;
    if (i >= n4) return;
    float4 v = ((const float4*)in)[i];
    __nv_bfloat16 h0, h1, h2, h3, l0, l1, l2, l3;
    split1(v.x, h0, l0); split1(v.y, h1, l1);
    split1(v.z, h2, l2); split1(v.w, h3, l3);
    ((__nv_bfloat162*)hi)[2 * i]     = __nv_bfloat162(h0, h1);
    ((__nv_bfloat162*)hi)[2 * i + 1] = __nv_bfloat162(h2, h3);
    ((__nv_bfloat162*)lo)[2 * i]     = __nv_bfloat162(l0, l1);
    ((__nv_bfloat162*)lo)[2 * i + 1] = __nv_bfloat162(l2, l3);
}

// ---------------------------------------------------------------------------
// degree / scatter / combine
// ---------------------------------------------------------------------------
__global__ void deg_kernel(const int* __restrict__ dst, float* __restrict__ deg, int E) {
    int i = blockIdx.x * blockDim.x + threadIdx.x;
    if (i < E) atomicAdd(&deg[dst[i]], 1.0f);
}

__device__ __forceinline__ void red_add_v4(float* p, float4 v) {
    asm volatile("red.global.add.v4.f32 [%0], {%1, %2, %3, %4};"
                 :: "l"(p), "f"(v.x), "f"(v.y), "f"(v.z), "f"(v.w)
                 : "memory");
}

template <int D>
__global__ void scatter_add_kernel(const float* __restrict__ feat,
                                   const int* __restrict__ src,
                                   const int* __restrict__ dst,
                                   float* __restrict__ agg, int E) {
    int warp = (blockIdx.x * blockDim.x + threadIdx.x) >> 5;
    int lane = threadIdx.x & 31;
    if (warp >= E) return;
    int s = src[warp];
    int d = dst[warp];
    const float4* in = (const float4*)(feat + (size_t)s * D);
    float* outp = agg + (size_t)d * D;
#pragma unroll
    for (int i = 0; i < D / 128; i++) {
        int idx = lane + i * 32;
        float4 v = in[idx];
        red_add_v4(outp + idx * 4, v);
    }
}

// combine (+relu) then split into bf16 hi/lo (for layer-1 -> h)
template <int DQ>
__global__ void combine_split_kernel(const float* __restrict__ agg,
                                     const float* __restrict__ z,
                                     const float* __restrict__ deg,
                                     __nv_bfloat16* __restrict__ hhi,
                                     __nv_bfloat16* __restrict__ hlo, int total4) {
    int i = blockIdx.x * blockDim.x + threadIdx.x;
    if (i >= total4) return;
    int row = i / DQ;
    float sc = 1.0f / fmaxf(deg[row], 1.0f);
    float4 a = ((const float4*)agg)[i];
    float4 zz = ((const float4*)z)[i];
    float4 r;
    r.x = fmaxf(a.x * sc + zz.x, 0.f);
    r.y = fmaxf(a.y * sc + zz.y, 0.f);
    r.z = fmaxf(a.z * sc + zz.z, 0.f);
    r.w = fmaxf(a.w * sc + zz.w, 0.f);
    __nv_bfloat16 h0, h1, h2, h3, l0, l1, l2, l3;
    split1(r.x, h0, l0); split1(r.y, h1, l1);
    split1(r.z, h2, l2); split1(r.w, h3, l3);
    ((__nv_bfloat162*)hhi)[2 * i]     = __nv_bfloat162(h0, h1);
    ((__nv_bfloat162*)hhi)[2 * i + 1] = __nv_bfloat162(h2, h3);
    ((__nv_bfloat162*)hlo)[2 * i]     = __nv_bfloat162(l0, l1);
    ((__nv_bfloat162*)hlo)[2 * i + 1] = __nv_bfloat162(l2, l3);
}

// final combine (no relu), fp32 out
template <int DQ>
__global__ void combine_kernel(const float* __restrict__ agg,
                               const float* __restrict__ z,
                               const float* __restrict__ deg,
                               float* __restrict__ out, int total4) {
    int i = blockIdx.x * blockDim.x + threadIdx.x;
    if (i >= total4) return;
    int row = i / DQ;
    float sc = 1.0f / fmaxf(deg[row], 1.0f);
    float4 a = ((const float4*)agg)[i];
    float4 zz = ((const float4*)z)[i];
    float4 r;
    r.x = a.x * sc + zz.x;
    r.y = a.y * sc + zz.y;
    r.z = a.z * sc + zz.z;
    r.w = a.w * sc + zz.w;
    ((float4*)out)[i] = r;
}

// ---------------------------------------------------------------------------
extern "C" void kernel_launch(void* const* d_in, const int* in_sizes, int n_in,
                              void* d_out, int out_size) {
    const float* x    = (const float*)d_in[0];
    const int* eidx   = (const int*)d_in[1];
    const float* W1l  = (const float*)d_in[2];
    const float* b1   = (const float*)d_in[3];
    const float* W1r  = (const float*)d_in[4];
    const float* W2l  = (const float*)d_in[5];
    const float* b2   = (const float*)d_in[6];
    const float* W2r  = (const float*)d_in[7];
    float* out = (float*)d_out;

    const int N = in_sizes[0] / D1;
    const int E = in_sizes[1] / 2;
    const int* src = eidx;
    const int* dst = eidx + E;

    float *y1, *z1, *agg1, *y2, *z2, *agg2, *deg;
    __nv_bfloat16 *xhi, *xlo, *hhi, *hlo, *w;
    cudaGetSymbolAddress((void**)&y1,   g_y1);
    cudaGetSymbolAddress((void**)&z1,   g_z1);
    cudaGetSymbolAddress((void**)&agg1, g_agg1);
    cudaGetSymbolAddress((void**)&y2,   g_y2);
    cudaGetSymbolAddress((void**)&z2,   g_z2);
    cudaGetSymbolAddress((void**)&agg2, g_agg2);
    cudaGetSymbolAddress((void**)&deg,  g_deg);
    cudaGetSymbolAddress((void**)&xhi,  g_xhi);
    cudaGetSymbolAddress((void**)&xlo,  g_xlo);
    cudaGetSymbolAddress((void**)&hhi,  g_hhi);
    cudaGetSymbolAddress((void**)&hlo,  g_hlo);
    cudaGetSymbolAddress((void**)&w,    g_w);

    __nv_bfloat16* w1l_hi = w;
    __nv_bfloat16* w1l_lo = w + 65536;
    __nv_bfloat16* w1r_hi = w + 2 * 65536;
    __nv_bfloat16* w1r_lo = w + 3 * 65536;
    __nv_bfloat16* w2l_hi = w + 4 * 65536;
    __nv_bfloat16* w2l_lo = w + 4 * 65536 + 32768;
    __nv_bfloat16* w2r_hi = w + 4 * 65536 + 2 * 32768;
    __nv_bfloat16* w2r_lo = w + 4 * 65536 + 3 * 32768;

    cudaMemsetAsync(agg1, 0, (size_t)N * D1 * sizeof(float));
    cudaMemsetAsync(agg2, 0, (size_t)N * D2 * sizeof(float));
    cudaMemsetAsync(deg,  0, (size_t)N * sizeof(float));

    deg_kernel<<<(E + 255) / 256, 256>>>(dst, deg, E);

    // splits
    split_kernel<<<(N * (D1 / 4) + 255) / 256, 256>>>(x, xhi, xlo, N * (D1 / 4));
    split_kernel<<<(65536 / 4 + 255) / 256, 256>>>(W1l, w1l_hi, w1l_lo, 65536 / 4);
    split_kernel<<<(65536 / 4 + 255) / 256, 256>>>(W1r, w1r_hi, w1r_lo, 65536 / 4);
    split_kernel<<<(32768 / 4 + 255) / 256, 256>>>(W2l, w2l_hi, w2l_lo, 32768 / 4);
    split_kernel<<<(32768 / 4 + 255) / 256, 256>>>(W2r, w2r_hi, w2r_lo, 32768 / 4);

    const int mb = (N + 127) / 128;

    // Layer 1: y1 = x@W1l^T ; z1 = x@W1r^T + b1
    gemm_bf16x3<D1><<<dim3(4, mb), 256>>>(xhi, xlo, w1l_hi, w1l_lo,
                                          w1r_hi, w1r_lo, b1, y1, z1, N);

    int scatterBlocks = (E + 7) / 8;
    scatter_add_kernel<D1><<<scatterBlocks, 256>>>(y1, src, dst, agg1, E);

    int t1 = N * (D1 / 4);
    combine_split_kernel<D1 / 4><<<(t1 + 255) / 256, 256>>>(agg1, z1, deg, hhi, hlo, t1);

    // Layer 2: y2 = h@W2l^T ; z2 = h@W2r^T + b2
    gemm_bf16x3<D2><<<dim3(2, mb), 256>>>(hhi, hlo, w2l_hi, w2l_lo,
                                          w2r_hi, w2r_lo, b2, y2, z2, N);

    scatter_add_kernel<D2><<<scatterBlocks, 256>>>(y2, src, dst, agg2, E);

    int t2 = N * (D2 / 4);
    combine_kernel<D2 / 4><<<(t2 + 255) / 256, 256>>>(agg2, z2, deg, out, t2);
}

// round 4
// speedup vs baseline: 1.5911x; 1.1024x over previous
#include <cuda_runtime.h>
#include <cuda_bf16.h>
#include <cstdint>

#define D1 256
#define D2 128
#define K_DIM 256

static const int MAX_N = 100000;
static const int MAX_E = 1600000;

// fp32 scratch
__device__ float g_y1[MAX_N * D1];
__device__ float g_agg1[MAX_N * D1];
__device__ float g_y2[MAX_N * D2];
__device__ float g_agg2[MAX_N * D2];
__device__ float g_deg[MAX_N];
// bf16 split scratch
__device__ __nv_bfloat16 g_xhi[MAX_N * D1];
__device__ __nv_bfloat16 g_xlo[MAX_N * D1];
__device__ __nv_bfloat16 g_hhi[MAX_N * D1];
__device__ __nv_bfloat16 g_hlo[MAX_N * D1];
// weight splits: w1l_hi, w1l_lo, w1r_hi, w1r_lo (65536 each),
// w2_hi = [W2l;W2r] (65536), w2_lo (65536)
__device__ __nv_bfloat16 g_w[6 * 65536];

// ---------------------------------------------------------------------------
__device__ __forceinline__ uint32_t smem_to_u32(const void* p) {
    uint32_t a;
    asm("{ .reg .u64 t; cvta.to.shared.u64 t, %1; cvt.u32.u64 %0, t; }"
        : "=r"(a) : "l"(p));
    return a;
}

__device__ __forceinline__ void cp_async16(uint32_t saddr, const void* gaddr, uint32_t n) {
    asm volatile("cp.async.cg.shared.global [%0], [%1], 16, %2;"
                 :: "r"(saddr), "l"(gaddr), "r"(n) : "memory");
}

__device__ __forceinline__ void mma_bf16(float* c, const uint32_t* a, const uint32_t* b) {
    asm volatile(
        "mma.sync.aligned.m16n8k16.row.col.f32.bf16.bf16.f32 "
        "{%0,%1,%2,%3}, {%4,%5,%6,%7}, {%8,%9}, {%0,%1,%2,%3};"
        : "+f"(c[0]), "+f"(c[1]), "+f"(c[2]), "+f"(c[3])
        : "r"(a[0]), "r"(a[1]), "r"(a[2]), "r"(a[3]), "r"(b[0]), "r"(b[1]));
}

#define LDSM_X4(r, addr) \
    asm volatile("ldmatrix.sync.aligned.m8n8.x4.shared.b16 {%0,%1,%2,%3}, [%4];" \
                 : "=r"((r)[0]), "=r"((r)[1]), "=r"((r)[2]), "=r"((r)[3]) \
                 : "r"(addr))

// ---------------------------------------------------------------------------
// bf16x3 GEMM, 128 rows x 256 cols per CTA, K=256 (physical), 3 MMA terms
// per K-chunk: Ahi*Bhi + Alo*Bhi + Ahi*Blo.
// Output cols 0-127 -> outA, 128-255 -> outB. Optional bias and deg-fold
// (write deg' * (acc + bias)) per output.
// ---------------------------------------------------------------------------
#define ROWB 80
#define AHI_OFF 0
#define ALO_OFF (128 * ROWB)
#define BHI_OFF (256 * ROWB)
#define BLO_OFF (512 * ROWB)
#define STAGE_SZ (768 * ROWB)          // 61440 B
#define GEMM_SMEM (2 * STAGE_SZ)       // 122880 B

__global__ __launch_bounds__(256, 1)
void gemm3(const __nv_bfloat16* __restrict__ Ahi,
           const __nv_bfloat16* __restrict__ Alo,
           const __nv_bfloat16* __restrict__ Whi,   // 256 rows x 256
           const __nv_bfloat16* __restrict__ Wlo,
           float* __restrict__ outA, int ldA, const float* __restrict__ biasA, int foldA,
           float* __restrict__ outB, int ldB, const float* __restrict__ biasB, int foldB,
           const float* __restrict__ deg, int M) {
    extern __shared__ char smem[];
    const uint32_t sbase = smem_to_u32(smem);
    const int tid = threadIdx.x;
    const int wid = tid >> 5, lane = tid & 31;
    const int wr = wid >> 2;          // 0..1 : row 64-block
    const int wc = wid & 3;           // 0..3 : col 64-block
    const int m0 = (int)blockIdx.x * 128;

    float acc[4][8][4];
#pragma unroll
    for (int i = 0; i < 4; i++)
#pragma unroll
        for (int j = 0; j < 8; j++)
#pragma unroll
            for (int k = 0; k < 4; k++) acc[i][j][k] = 0.0f;

    auto issue = [&](int c, int stage) {
        const uint32_t s0 = sbase + (uint32_t)stage * STAGE_SZ;
        const int ke = c * 32;  // k element offset
        // A tiles: 128 rows x 32 elems (64B = 4 x 16B chunks per row)
#pragma unroll
        for (int i = 0; i < 2; i++) {
            int id = tid + i * 256;
            int row = id >> 2, cc = id & 3;
            int gm = m0 + row;
            uint32_t p = (gm < M) ? 16u : 0u;
            const size_t goff = (size_t)gm * K_DIM + ke + cc * 8;
            cp_async16(s0 + AHI_OFF + row * ROWB + cc * 16, Ahi + goff, p);
            cp_async16(s0 + ALO_OFF + row * ROWB + cc * 16, Alo + goff, p);
        }
        // B tiles: 256 rows x 32 elems
#pragma unroll
        for (int i = 0; i < 4; i++) {
            int id = tid + i * 256;
            int row = id >> 2, cc = id & 3;
            const size_t goff = (size_t)row * K_DIM + ke + cc * 8;
            cp_async16(s0 + BHI_OFF + row * ROWB + cc * 16, Whi + goff, 16u);
            cp_async16(s0 + BLO_OFF + row * ROWB + cc * 16, Wlo + goff, 16u);
        }
        asm volatile("cp.async.commit_group;" ::: "memory");
    };

    issue(0, 0);
    for (int c = 0; c < 8; c++) {
        if (c + 1 < 8) {
            issue(c + 1, (c + 1) & 1);
            asm volatile("cp.async.wait_group 1;" ::: "memory");
        } else {
            asm volatile("cp.async.wait_group 0;" ::: "memory");
        }
        __syncthreads();

        const uint32_t s0 = sbase + (uint32_t)(c & 1) * STAGE_SZ;
#pragma unroll
        for (int s = 0; s < 2; s++) {
            const uint32_t aoff = s0 + (uint32_t)(wr * 64 + (lane & 15)) * ROWB
                                  + ((lane >> 4) << 4) + s * 32;
            const uint32_t boff = s0 + BHI_OFF
                                  + (uint32_t)(wc * 64 + (lane & 7) + ((lane >> 4) << 3)) * ROWB
                                  + (((lane >> 3) & 1) << 4) + s * 32;
            uint32_t ahi[4][4], alo[4][4], bb[4][4];
#pragma unroll
            for (int mi = 0; mi < 4; mi++) {
                LDSM_X4(ahi[mi], aoff + AHI_OFF + mi * (16 * ROWB));
                LDSM_X4(alo[mi], aoff + ALO_OFF + mi * (16 * ROWB));
            }
#pragma unroll
            for (int p = 0; p < 4; p++) LDSM_X4(bb[p], boff + p * (16 * ROWB));
            // term 1: ahi * bhi ; term 2: alo * bhi
#pragma unroll
            for (int mi = 0; mi < 4; mi++)
#pragma unroll
                for (int p = 0; p < 4; p++) {
                    mma_bf16(acc[mi][2 * p],     ahi[mi], &bb[p][0]);
                    mma_bf16(acc[mi][2 * p + 1], ahi[mi], &bb[p][2]);
                    mma_bf16(acc[mi][2 * p],     alo[mi], &bb[p][0]);
                    mma_bf16(acc[mi][2 * p + 1], alo[mi], &bb[p][2]);
                }
            // term 3: ahi * blo
#pragma unroll
            for (int p = 0; p < 4; p++) LDSM_X4(bb[p], boff + (BLO_OFF - BHI_OFF) + p * (16 * ROWB));
#pragma unroll
            for (int mi = 0; mi < 4; mi++)
#pragma unroll
                for (int p = 0; p < 4; p++) {
                    mma_bf16(acc[mi][2 * p],     ahi[mi], &bb[p][0]);
                    mma_bf16(acc[mi][2 * p + 1], ahi[mi], &bb[p][2]);
                }
        }
        __syncthreads();
    }

    // Epilogue — per-warp uniform output select
    const bool isB = (wc >= 2);
    float* out = isB ? outB : outA;
    const int ld = isB ? ldB : ldA;
    const float* bias = isB ? biasB : biasA;
    const int fold = isB ? foldB : foldA;
    const int cbase = wc * 64 - (isB ? 128 : 0);

#pragma unroll
    for (int mi = 0; mi < 4; mi++) {
        int r0 = m0 + wr * 64 + mi * 16 + (lane >> 2);
        int r1 = r0 + 8;
        float d0 = 1.0f, d1 = 1.0f;
        if (fold) {
            if (r0 < M) d0 = fmaxf(deg[r0], 1.0f);
            if (r1 < M) d1 = fmaxf(deg[r1], 1.0f);
        }
#pragma unroll
        for (int ni = 0; ni < 8; ni++) {
            int col = cbase + ni * 8 + 2 * (lane & 3);
            float bx = 0.f, by = 0.f;
            if (bias) { bx = __ldg(bias + col); by = __ldg(bias + col + 1); }
            if (r0 < M)
                *(float2*)(out + (size_t)r0 * ld + col) =
                    make_float2((acc[mi][ni][0] + bx) * d0, (acc[mi][ni][1] + by) * d0);
            if (r1 < M)
                *(float2*)(out + (size_t)r1 * ld + col) =
                    make_float2((acc[mi][ni][2] + bx) * d1, (acc[mi][ni][3] + by) * d1);
        }
    }
}

// ---------------------------------------------------------------------------
// fp32 -> (bf16 hi, bf16 lo) split
// ---------------------------------------------------------------------------
__device__ __forceinline__ void split1(float v, __nv_bfloat16& h, __nv_bfloat16& l) {
    h = __float2bfloat16(v);
    l = __float2bfloat16(v - __bfloat162float(h));
}

__global__ void split_kernel(const float* __restrict__ in,
                             __nv_bfloat16* __restrict__ hi,
                             __nv_bfloat16* __restrict__ lo, int n4) {
    int i = blockIdx.x * blockDim.x + threadIdx.x;
    if (i >= n4) return;
    float4 v = ((const float4*)in)[i];
    __nv_bfloat16 h0, h1, h2, h3, l0, l1, l2, l3;
    split1(v.x, h0, l0); split1(v.y, h1, l1);
    split1(v.z, h2, l2); split1(v.w, h3, l3);
    ((__nv_bfloat162*)hi)[2 * i]     = __nv_bfloat162(h0, h1);
    ((__nv_bfloat162*)hi)[2 * i + 1] = __nv_bfloat162(h2, h3);
    ((__nv_bfloat162*)lo)[2 * i]     = __nv_bfloat162(l0, l1);
    ((__nv_bfloat162*)lo)[2 * i + 1] = __nv_bfloat162(l2, l3);
}

// ---------------------------------------------------------------------------
__global__ void deg_kernel(const int* __restrict__ dst, float* __restrict__ deg, int E) {
    int i = blockIdx.x * blockDim.x + threadIdx.x;
    if (i < E) atomicAdd(&deg[dst[i]], 1.0f);
}

__device__ __forceinline__ void red_add_v4(float* p, float4 v) {
    asm volatile("red.global.add.v4.f32 [%0], {%1, %2, %3, %4};"
                 :: "l"(p), "f"(v.x), "f"(v.y), "f"(v.z), "f"(v.w)
                 : "memory");
}

// one warp per edge, 128 contiguous columns starting at c0 (L2-tiled pass)
template <int D>
__global__ void scatter_half(const float* __restrict__ feat,
                             const int* __restrict__ src,
                             const int* __restrict__ dst,
                             float* __restrict__ agg, int E, int c0) {
    int warp = (blockIdx.x * blockDim.x + threadIdx.x) >> 5;
    int lane = threadIdx.x & 31;
    if (warp >= E) return;
    int s = src[warp];
    int d = dst[warp];
    float4 v = *((const float4*)(feat + (size_t)s * D + c0) + lane);
    red_add_v4(agg + (size_t)d * D + c0 + lane * 4, v);
}

// h = relu(agg / deg'), split to bf16 hi/lo  (agg pre-initialized to deg'*z)
template <int DQ>
__global__ void combine_split_kernel(const float* __restrict__ agg,
                                     const float* __restrict__ deg,
                                     __nv_bfloat16* __restrict__ hhi,
                                     __nv_bfloat16* __restrict__ hlo, int total4) {
    int i = blockIdx.x * blockDim.x + threadIdx.x;
    if (i >= total4) return;
    int row = i / DQ;
    float sc = 1.0f / fmaxf(deg[row], 1.0f);
    float4 a = ((const float4*)agg)[i];
    float4 r;
    r.x = fmaxf(a.x * sc, 0.f);
    r.y = fmaxf(a.y * sc, 0.f);
    r.z = fmaxf(a.z * sc, 0.f);
    r.w = fmaxf(a.w * sc, 0.f);
    __nv_bfloat16 h0, h1, h2, h3, l0, l1, l2, l3;
    split1(r.x, h0, l0); split1(r.y, h1, l1);
    split1(r.z, h2, l2); split1(r.w, h3, l3);
    ((__nv_bfloat162*)hhi)[2 * i]     = __nv_bfloat162(h0, h1);
    ((__nv_bfloat162*)hhi)[2 * i + 1] = __nv_bfloat162(h2, h3);
    ((__nv_bfloat162*)hlo)[2 * i]     = __nv_bfloat162(l0, l1);
    ((__nv_bfloat162*)hlo)[2 * i + 1] = __nv_bfloat162(l2, l3);
}

// out = agg / deg'
template <int DQ>
__global__ void combine_final_kernel(const float* __restrict__ agg,
                                     const float* __restrict__ deg,
                                     float* __restrict__ out, int total4) {
    int i = blockIdx.x * blockDim.x + threadIdx.x;
    if (i >= total4) return;
    int row = i / DQ;
    float sc = 1.0f / fmaxf(deg[row], 1.0f);
    float4 a = ((const float4*)agg)[i];
    ((float4*)out)[i] = make_float4(a.x * sc, a.y * sc, a.z * sc, a.w * sc);
}

// ---------------------------------------------------------------------------
extern "C" void kernel_launch(void* const* d_in, const int* in_sizes, int n_in,
                              void* d_out, int out_size) {
    const float* x    = (const float*)d_in[0];
    const int* eidx   = (const int*)d_in[1];
    const float* W1l  = (const float*)d_in[2];
    const float* b1   = (const float*)d_in[3];
    const float* W1r  = (const float*)d_in[4];
    const float* W2l  = (const float*)d_in[5];
    const float* b2   = (const float*)d_in[6];
    const float* W2r  = (const float*)d_in[7];
    float* out = (float*)d_out;

    const int N = in_sizes[0] / D1;
    const int E = in_sizes[1] / 2;
    const int* src = eidx;
    const int* dst = eidx + E;

    float *y1, *agg1, *y2, *agg2, *deg;
    __nv_bfloat16 *xhi, *xlo, *hhi, *hlo, *w;
    cudaGetSymbolAddress((void**)&y1,   g_y1);
    cudaGetSymbolAddress((void**)&agg1, g_agg1);
    cudaGetSymbolAddress((void**)&y2,   g_y2);
    cudaGetSymbolAddress((void**)&agg2, g_agg2);
    cudaGetSymbolAddress((void**)&deg,  g_deg);
    cudaGetSymbolAddress((void**)&xhi,  g_xhi);
    cudaGetSymbolAddress((void**)&xlo,  g_xlo);
    cudaGetSymbolAddress((void**)&hhi,  g_hhi);
    cudaGetSymbolAddress((void**)&hlo,  g_hlo);
    cudaGetSymbolAddress((void**)&w,    g_w);

    __nv_bfloat16* w1l_hi = w;
    __nv_bfloat16* w1l_lo = w + 65536;
    __nv_bfloat16* w1r_hi = w + 2 * 65536;
    __nv_bfloat16* w1r_lo = w + 3 * 65536;
    __nv_bfloat16* w2_hi  = w + 4 * 65536;   // [W2l ; W2r] stacked (256 rows)
    __nv_bfloat16* w2_lo  = w + 5 * 65536;

    cudaFuncSetAttribute(gemm3, cudaFuncAttributeMaxDynamicSharedMemorySize, GEMM_SMEM);

    cudaMemsetAsync(deg, 0, (size_t)N * sizeof(float));
    deg_kernel<<<(E + 255) / 256, 256>>>(dst, deg, E);

    // splits
    split_kernel<<<(N * (D1 / 4) + 255) / 256, 256>>>(x, xhi, xlo, N * (D1 / 4));
    split_kernel<<<64, 256>>>(W1l, w1l_hi, w1l_lo, 65536 / 4);
    split_kernel<<<64, 256>>>(W1r, w1r_hi, w1r_lo, 65536 / 4);
    split_kernel<<<32, 256>>>(W2l, w2_hi, w2_lo, 32768 / 4);
    split_kernel<<<32, 256>>>(W2r, w2_hi + 32768, w2_lo + 32768, 32768 / 4);

    const int mb = (N + 127) / 128;

    // Layer 1: y1 = x@W1l^T (plain); agg1 init = deg' * (x@W1r^T + b1)
    gemm3<<<mb, 256, GEMM_SMEM>>>(xhi, xlo, w1l_hi, w1l_lo,
                                  y1, D1, nullptr, 0,
                                  y1 + 128, D1, nullptr, 0, deg, N);
    gemm3<<<mb, 256, GEMM_SMEM>>>(xhi, xlo, w1r_hi, w1r_lo,
                                  agg1, D1, b1, 1,
                                  agg1 + 128, D1, b1 + 128, 1, deg, N);

    int scatterBlocks = (E + 7) / 8;
    scatter_half<D1><<<scatterBlocks, 256>>>(y1, src, dst, agg1, E, 0);
    scatter_half<D1><<<scatterBlocks, 256>>>(y1, src, dst, agg1, E, 128);

    int t1 = N * (D1 / 4);
    combine_split_kernel<D1 / 4><<<(t1 + 255) / 256, 256>>>(agg1, deg, hhi, hlo, t1);

    // Layer 2: cols 0-127 -> y2 (plain); cols 128-255 -> agg2 = deg'*(h@W2r^T + b2)
    gemm3<<<mb, 256, GEMM_SMEM>>>(hhi, hlo, w2_hi, w2_lo,
                                  y2, D2, nullptr, 0,
                                  agg2, D2, b2, 1, deg, N);

    scatter_half<D2><<<scatterBlocks, 256>>>(y2, src, dst, agg2, E, 0);

    int t2 = N * (D2 / 4);
    combine_final_kernel<D2 / 4><<<(t2 + 255) / 256, 256>>>(agg2, deg, out, t2);
}

// round 5
// speedup vs baseline: 2.2728x; 1.4284x over previous
#include <cuda_runtime.h>
#include <cuda_bf16.h>
#include <cstdint>

#define D1 256
#define D2 128
#define K_DIM 256

static const int MAX_N = 100000;
static const int MAX_E = 1600000;

// fp32 scratch
__device__ float g_y1[MAX_N * D1];   // x @ W1l^T
__device__ float g_z1[MAX_N * D1];   // x @ W1r^T + b1
__device__ float g_y2[MAX_N * D2];   // h @ W2l^T
__device__ float g_z2[MAX_N * D2];   // h @ W2r^T + b2
__device__ float g_deg[MAX_N];
// bf16 split scratch
__device__ __nv_bfloat16 g_xhi[MAX_N * D1];
__device__ __nv_bfloat16 g_xlo[MAX_N * D1];
__device__ __nv_bfloat16 g_hhi[MAX_N * D1];
__device__ __nv_bfloat16 g_hlo[MAX_N * D1];
// weight splits: w1l_hi, w1l_lo, w1r_hi, w1r_lo (65536 each),
// w2_hi = [W2l;W2r] (65536), w2_lo (65536)
__device__ __nv_bfloat16 g_w[6 * 65536];
// CSR
__device__ int g_rowptr[MAX_N];
__device__ int g_cursor[MAX_N];
__device__ int g_csr[MAX_E];
__device__ int g_bsum[128];
__device__ int g_boff[128];

#define SCAN_BLK 1024   // elements per scan block
#define SCAN_NB  ((MAX_N + SCAN_BLK - 1) / SCAN_BLK)   // 98

// ---------------------------------------------------------------------------
__device__ __forceinline__ uint32_t smem_to_u32(const void* p) {
    uint32_t a;
    asm("{ .reg .u64 t; cvta.to.shared.u64 t, %1; cvt.u32.u64 %0, t; }"
        : "=r"(a) : "l"(p));
    return a;
}

__device__ __forceinline__ void cp_async16(uint32_t saddr, const void* gaddr, uint32_t n) {
    asm volatile("cp.async.cg.shared.global [%0], [%1], 16, %2;"
                 :: "r"(saddr), "l"(gaddr), "r"(n) : "memory");
}

__device__ __forceinline__ void mma_bf16(float* c, const uint32_t* a, const uint32_t* b) {
    asm volatile(
        "mma.sync.aligned.m16n8k16.row.col.f32.bf16.bf16.f32 "
        "{%0,%1,%2,%3}, {%4,%5,%6,%7}, {%8,%9}, {%0,%1,%2,%3};"
        : "+f"(c[0]), "+f"(c[1]), "+f"(c[2]), "+f"(c[3])
        : "r"(a[0]), "r"(a[1]), "r"(a[2]), "r"(a[3]), "r"(b[0]), "r"(b[1]));
}

#define LDSM_X4(r, addr) \
    asm volatile("ldmatrix.sync.aligned.m8n8.x4.shared.b16 {%0,%1,%2,%3}, [%4];" \
                 : "=r"((r)[0]), "=r"((r)[1]), "=r"((r)[2]), "=r"((r)[3]) \
                 : "r"(addr))

// ---------------------------------------------------------------------------
// bf16x3 GEMM, 128 rows x 256 cols per CTA, 3 MMA terms per K-chunk.
// Output cols 0-127 -> outA, 128-255 -> outB (+ optional bias each).
// ---------------------------------------------------------------------------
#define ROWB 80
#define AHI_OFF 0
#define ALO_OFF (128 * ROWB)
#define BHI_OFF (256 * ROWB)
#define BLO_OFF (512 * ROWB)
#define STAGE_SZ (768 * ROWB)
#define GEMM_SMEM (2 * STAGE_SZ)

__global__ __launch_bounds__(256, 1)
void gemm3(const __nv_bfloat16* __restrict__ Ahi,
           const __nv_bfloat16* __restrict__ Alo,
           const __nv_bfloat16* __restrict__ Whi,   // 256 rows x 256
           const __nv_bfloat16* __restrict__ Wlo,
           float* __restrict__ outA, int ldA, const float* __restrict__ biasA,
           float* __restrict__ outB, int ldB, const float* __restrict__ biasB,
           int M) {
    extern __shared__ char smem[];
    const uint32_t sbase = smem_to_u32(smem);
    const int tid = threadIdx.x;
    const int wid = tid >> 5, lane = tid & 31;
    const int wr = wid >> 2;
    const int wc = wid & 3;
    const int m0 = (int)blockIdx.x * 128;

    float acc[4][8][4];
#pragma unroll
    for (int i = 0; i < 4; i++)
#pragma unroll
        for (int j = 0; j < 8; j++)
#pragma unroll
            for (int k = 0; k < 4; k++) acc[i][j][k] = 0.0f;

    auto issue = [&](int c, int stage) {
        const uint32_t s0 = sbase + (uint32_t)stage * STAGE_SZ;
        const int ke = c * 32;
#pragma unroll
        for (int i = 0; i < 2; i++) {
            int id = tid + i * 256;
            int row = id >> 2, cc = id & 3;
            int gm = m0 + row;
            uint32_t p = (gm < M) ? 16u : 0u;
            const size_t goff = (size_t)gm * K_DIM + ke + cc * 8;
            cp_async16(s0 + AHI_OFF + row * ROWB + cc * 16, Ahi + goff, p);
            cp_async16(s0 + ALO_OFF + row * ROWB + cc * 16, Alo + goff, p);
        }
#pragma unroll
        for (int i = 0; i < 4; i++) {
            int id = tid + i * 256;
            int row = id >> 2, cc = id & 3;
            const size_t goff = (size_t)row * K_DIM + ke + cc * 8;
            cp_async16(s0 + BHI_OFF + row * ROWB + cc * 16, Whi + goff, 16u);
            cp_async16(s0 + BLO_OFF + row * ROWB + cc * 16, Wlo + goff, 16u);
        }
        asm volatile("cp.async.commit_group;" ::: "memory");
    };

    issue(0, 0);
    for (int c = 0; c < 8; c++) {
        if (c + 1 < 8) {
            issue(c + 1, (c + 1) & 1);
            asm volatile("cp.async.wait_group 1;" ::: "memory");
        } else {
            asm volatile("cp.async.wait_group 0;" ::: "memory");
        }
        __syncthreads();

        const uint32_t s0 = sbase + (uint32_t)(c & 1) * STAGE_SZ;
#pragma unroll
        for (int s = 0; s < 2; s++) {
            const uint32_t aoff = s0 + (uint32_t)(wr * 64 + (lane & 15)) * ROWB
                                  + ((lane >> 4) << 4) + s * 32;
            const uint32_t boff = s0 + BHI_OFF
                                  + (uint32_t)(wc * 64 + (lane & 7) + ((lane >> 4) << 3)) * ROWB
                                  + (((lane >> 3) & 1) << 4) + s * 32;
            uint32_t ahi[4][4], alo[4][4], bb[4][4];
#pragma unroll
            for (int mi = 0; mi < 4; mi++) {
                LDSM_X4(ahi[mi], aoff + AHI_OFF + mi * (16 * ROWB));
                LDSM_X4(alo[mi], aoff + ALO_OFF + mi * (16 * ROWB));
            }
#pragma unroll
            for (int p = 0; p < 4; p++) LDSM_X4(bb[p], boff + p * (16 * ROWB));
#pragma unroll
            for (int mi = 0; mi < 4; mi++)
#pragma unroll
                for (int p = 0; p < 4; p++) {
                    mma_bf16(acc[mi][2 * p],     ahi[mi], &bb[p][0]);
                    mma_bf16(acc[mi][2 * p + 1], ahi[mi], &bb[p][2]);
                    mma_bf16(acc[mi][2 * p],     alo[mi], &bb[p][0]);
                    mma_bf16(acc[mi][2 * p + 1], alo[mi], &bb[p][2]);
                }
#pragma unroll
            for (int p = 0; p < 4; p++) LDSM_X4(bb[p], boff + (BLO_OFF - BHI_OFF) + p * (16 * ROWB));
#pragma unroll
            for (int mi = 0; mi < 4; mi++)
#pragma unroll
                for (int p = 0; p < 4; p++) {
                    mma_bf16(acc[mi][2 * p],     ahi[mi], &bb[p][0]);
                    mma_bf16(acc[mi][2 * p + 1], ahi[mi], &bb[p][2]);
                }
        }
        __syncthreads();
    }

    const bool isB = (wc >= 2);
    float* out = isB ? outB : outA;
    const int ld = isB ? ldB : ldA;
    const float* bias = isB ? biasB : biasA;
    const int cbase = wc * 64 - (isB ? 128 : 0);

#pragma unroll
    for (int mi = 0; mi < 4; mi++) {
        int r0 = m0 + wr * 64 + mi * 16 + (lane >> 2);
        int r1 = r0 + 8;
#pragma unroll
        for (int ni = 0; ni < 8; ni++) {
            int col = cbase + ni * 8 + 2 * (lane & 3);
            float bx = 0.f, by = 0.f;
            if (bias) { bx = __ldg(bias + col); by = __ldg(bias + col + 1); }
            if (r0 < M)
                *(float2*)(out + (size_t)r0 * ld + col) =
                    make_float2(acc[mi][ni][0] + bx, acc[mi][ni][1] + by);
            if (r1 < M)
                *(float2*)(out + (size_t)r1 * ld + col) =
                    make_float2(acc[mi][ni][2] + bx, acc[mi][ni][3] + by);
        }
    }
}

// ---------------------------------------------------------------------------
// splits
// ---------------------------------------------------------------------------
__device__ __forceinline__ void split1(float v, __nv_bfloat16& h, __nv_bfloat16& l) {
    h = __float2bfloat16(v);
    l = __float2bfloat16(v - __bfloat162float(h));
}

__global__ void split_kernel(const float* __restrict__ in,
                             __nv_bfloat16* __restrict__ hi,
                             __nv_bfloat16* __restrict__ lo, int n4) {
    int i = blockIdx.x * blockDim.x + threadIdx.x;
    if (i >= n4) return;
    float4 v = ((const float4*)in)[i];
    __nv_bfloat16 h0, h1, h2, h3, l0, l1, l2, l3;
    split1(v.x, h0, l0); split1(v.y, h1, l1);
    split1(v.z, h2, l2); split1(v.w, h3, l3);
    ((__nv_bfloat162*)hi)[2 * i]     = __nv_bfloat162(h0, h1);
    ((__nv_bfloat162*)hi)[2 * i + 1] = __nv_bfloat162(h2, h3);
    ((__nv_bfloat162*)lo)[2 * i]     = __nv_bfloat162(l0, l1);
    ((__nv_bfloat162*)lo)[2 * i + 1] = __nv_bfloat162(l2, l3);
}

// all four weight matrices in one launch
__global__ void wsplit_all(const float* __restrict__ W1l, const float* __restrict__ W1r,
                           const float* __restrict__ W2l, const float* __restrict__ W2r,
                           __nv_bfloat16* __restrict__ w) {
    int i = blockIdx.x * blockDim.x + threadIdx.x;   // float4 index, total 49152
    const float* src;
    __nv_bfloat16 *hi, *lo;
    int base;
    if (i < 16384)      { src = W1l; base = i;          hi = w;               lo = w + 65536; }
    else if (i < 32768) { src = W1r; base = i - 16384;  hi = w + 2 * 65536;   lo = w + 3 * 65536; }
    else if (i < 40960) { src = W2l; base = i - 32768;  hi = w + 4 * 65536;   lo = w + 5 * 65536; }
    else if (i < 49152) { src = W2r; base = i - 40960;  hi = w + 4 * 65536 + 32768; lo = w + 5 * 65536 + 32768; }
    else return;
    float4 v = ((const float4*)src)[base];
    __nv_bfloat16 h0, h1, h2, h3, l0, l1, l2, l3;
    split1(v.x, h0, l0); split1(v.y, h1, l1);
    split1(v.z, h2, l2); split1(v.w, h3, l3);
    ((__nv_bfloat162*)hi)[2 * base]     = __nv_bfloat162(h0, h1);
    ((__nv_bfloat162*)hi)[2 * base + 1] = __nv_bfloat162(h2, h3);
    ((__nv_bfloat162*)lo)[2 * base]     = __nv_bfloat162(l0, l1);
    ((__nv_bfloat162*)lo)[2 * base + 1] = __nv_bfloat162(l2, l3);
}

// ---------------------------------------------------------------------------
// degree + CSR build
// ---------------------------------------------------------------------------
__global__ void deg_kernel(const int* __restrict__ dst, float* __restrict__ deg, int E) {
    int i = blockIdx.x * blockDim.x + threadIdx.x;
    if (i < E) atomicAdd(&deg[dst[i]], 1.0f);
}

// partial sums: each block sums SCAN_BLK ints (from float deg)
__global__ void scan_part(const float* __restrict__ deg, int* __restrict__ bsum, int N) {
    __shared__ int sm[256];
    int b = blockIdx.x;
    int t = threadIdx.x;
    int s = 0;
#pragma unroll
    for (int k = 0; k < 4; k++) {
        int i = b * SCAN_BLK + t * 4 + k;
        if (i < N) s += (int)deg[i];
    }
    sm[t] = s;
    __syncthreads();
    for (int o = 128; o > 0; o >>= 1) {
        if (t < o) sm[t] += sm[t + o];
        __syncthreads();
    }
    if (t == 0) bsum[b] = sm[0];
}

// single-block exclusive scan of block sums
__global__ void scan_sums(const int* __restrict__ bsum, int* __restrict__ boff, int nb) {
    __shared__ int sm[128];
    int t = threadIdx.x;
    sm[t] = (t < nb) ? bsum[t] : 0;
    __syncthreads();
    // Hillis-Steele inclusive
    for (int o = 1; o < 128; o <<= 1) {
        int v = (t >= o) ? sm[t - o] : 0;
        __syncthreads();
        sm[t] += v;
        __syncthreads();
    }
    if (t < nb) boff[t] = (t == 0) ? 0 : sm[t - 1];
}

// write rowptr + cursor
__global__ void scan_write(const float* __restrict__ deg, const int* __restrict__ boff,
                           int* __restrict__ rowptr, int* __restrict__ cursor, int N) {
    __shared__ int sm[256];
    int b = blockIdx.x;
    int t = threadIdx.x;
    int d[4];
    int s = 0;
#pragma unroll
    for (int k = 0; k < 4; k++) {
        int i = b * SCAN_BLK + t * 4 + k;
        d[k] = (i < N) ? (int)deg[i] : 0;
        s += d[k];
    }
    sm[t] = s;
    __syncthreads();
    for (int o = 1; o < 256; o <<= 1) {
        int v = (t >= o) ? sm[t - o] : 0;
        __syncthreads();
        sm[t] += v;
        __syncthreads();
    }
    int off = boff[b] + ((t == 0) ? 0 : sm[t - 1]);
#pragma unroll
    for (int k = 0; k < 4; k++) {
        int i = b * SCAN_BLK + t * 4 + k;
        if (i < N) { rowptr[i] = off; cursor[i] = off; }
        off += d[k];
    }
}

__global__ void fill_csr(const int* __restrict__ src, const int* __restrict__ dst,
                         int* __restrict__ cursor, int* __restrict__ csr, int E) {
    int i = blockIdx.x * blockDim.x + threadIdx.x;
    if (i >= E) return;
    int pos = atomicAdd(&cursor[dst[i]], 1);
    csr[pos] = src[i];
}

// ---------------------------------------------------------------------------
// CSR gather, layer 1: h = relu(mean_gather(y1)/1 + z1), split to bf16 hi/lo
// One warp per (node, 128-col half).
// ---------------------------------------------------------------------------
__global__ void gather1(const float* __restrict__ y, const float* __restrict__ z,
                        const int* __restrict__ rowptr, const int* __restrict__ csr,
                        const float* __restrict__ deg,
                        __nv_bfloat16* __restrict__ hhi, __nv_bfloat16* __restrict__ hlo,
                        int N) {
    int gw = (blockIdx.x * blockDim.x + threadIdx.x) >> 5;
    int lane = threadIdx.x & 31;
    int node = gw >> 1;
    int c0 = (gw & 1) * 128;
    if (node >= N) return;

    int start = rowptr[node];
    float degf = deg[node];
    int cnt = (int)degf;
    float4 acc = make_float4(0.f, 0.f, 0.f, 0.f);
    for (int j0 = 0; j0 < cnt; j0 += 32) {
        int m = min(32, cnt - j0);
        int sid = (lane < m) ? csr[start + j0 + lane] : 0;
        for (int t = 0; t < m; t++) {
            int sN = __shfl_sync(0xffffffff, sid, t);
            float4 v = *(const float4*)(y + (size_t)sN * D1 + c0 + lane * 4);
            acc.x += v.x; acc.y += v.y; acc.z += v.z; acc.w += v.w;
        }
    }
    float sc = 1.0f / fmaxf(degf, 1.0f);
    float4 zz = *(const float4*)(z + (size_t)node * D1 + c0 + lane * 4);
    float4 r;
    r.x = fmaxf(acc.x * sc + zz.x, 0.f);
    r.y = fmaxf(acc.y * sc + zz.y, 0.f);
    r.z = fmaxf(acc.z * sc + zz.z, 0.f);
    r.w = fmaxf(acc.w * sc + zz.w, 0.f);
    __nv_bfloat16 h0, h1, h2, h3, l0, l1, l2, l3;
    split1(r.x, h0, l0); split1(r.y, h1, l1);
    split1(r.z, h2, l2); split1(r.w, h3, l3);
    size_t o = (size_t)node * D1 + c0 + lane * 4;
    *(__nv_bfloat162*)(hhi + o)     = __nv_bfloat162(h0, h1);
    *(__nv_bfloat162*)(hhi + o + 2) = __nv_bfloat162(h2, h3);
    *(__nv_bfloat162*)(hlo + o)     = __nv_bfloat162(l0, l1);
    *(__nv_bfloat162*)(hlo + o + 2) = __nv_bfloat162(l2, l3);
}

// layer 2: out = mean_gather(y2) + z2 (no relu), fp32. One warp per node.
__global__ void gather2(const float* __restrict__ y, const float* __restrict__ z,
                        const int* __restrict__ rowptr, const int* __restrict__ csr,
                        const float* __restrict__ deg,
                        float* __restrict__ out, int N) {
    int node = (blockIdx.x * blockDim.x + threadIdx.x) >> 5;
    int lane = threadIdx.x & 31;
    if (node >= N) return;

    int start = rowptr[node];
    float degf = deg[node];
    int cnt = (int)degf;
    float4 acc = make_float4(0.f, 0.f, 0.f, 0.f);
    for (int j0 = 0; j0 < cnt; j0 += 32) {
        int m = min(32, cnt - j0);
        int sid = (lane < m) ? csr[start + j0 + lane] : 0;
        for (int t = 0; t < m; t++) {
            int sN = __shfl_sync(0xffffffff, sid, t);
            float4 v = *(const float4*)(y + (size_t)sN * D2 + lane * 4);
            acc.x += v.x; acc.y += v.y; acc.z += v.z; acc.w += v.w;
        }
    }
    float sc = 1.0f / fmaxf(degf, 1.0f);
    float4 zz = *(const float4*)(z + (size_t)node * D2 + lane * 4);
    *(float4*)(out + (size_t)node * D2 + lane * 4) =
        make_float4(acc.x * sc + zz.x, acc.y * sc + zz.y,
                    acc.z * sc + zz.z, acc.w * sc + zz.w);
}

// ---------------------------------------------------------------------------
extern "C" void kernel_launch(void* const* d_in, const int* in_sizes, int n_in,
                              void* d_out, int out_size) {
    const float* x    = (const float*)d_in[0];
    const int* eidx   = (const int*)d_in[1];
    const float* W1l  = (const float*)d_in[2];
    const float* b1   = (const float*)d_in[3];
    const float* W1r  = (const float*)d_in[4];
    const float* W2l  = (const float*)d_in[5];
    const float* b2   = (const float*)d_in[6];
    const float* W2r  = (const float*)d_in[7];
    float* out = (float*)d_out;

    const int N = in_sizes[0] / D1;
    const int E = in_sizes[1] / 2;
    const int* src = eidx;
    const int* dst = eidx + E;

    float *y1, *z1, *y2, *z2, *deg;
    __nv_bfloat16 *xhi, *xlo, *hhi, *hlo, *w;
    int *rowptr, *cursor, *csr, *bsum, *boff;
    cudaGetSymbolAddress((void**)&y1,   g_y1);
    cudaGetSymbolAddress((void**)&z1,   g_z1);
    cudaGetSymbolAddress((void**)&y2,   g_y2);
    cudaGetSymbolAddress((void**)&z2,   g_z2);
    cudaGetSymbolAddress((void**)&deg,  g_deg);
    cudaGetSymbolAddress((void**)&xhi,  g_xhi);
    cudaGetSymbolAddress((void**)&xlo,  g_xlo);
    cudaGetSymbolAddress((void**)&hhi,  g_hhi);
    cudaGetSymbolAddress((void**)&hlo,  g_hlo);
    cudaGetSymbolAddress((void**)&w,    g_w);
    cudaGetSymbolAddress((void**)&rowptr, g_rowptr);
    cudaGetSymbolAddress((void**)&cursor, g_cursor);
    cudaGetSymbolAddress((void**)&csr,    g_csr);
    cudaGetSymbolAddress((void**)&bsum,   g_bsum);
    cudaGetSymbolAddress((void**)&boff,   g_boff);

    __nv_bfloat16* w1l_hi = w;
    __nv_bfloat16* w1l_lo = w + 65536;
    __nv_bfloat16* w1r_hi = w + 2 * 65536;
    __nv_bfloat16* w1r_lo = w + 3 * 65536;
    __nv_bfloat16* w2_hi  = w + 4 * 65536;
    __nv_bfloat16* w2_lo  = w + 5 * 65536;

    cudaFuncSetAttribute(gemm3, cudaFuncAttributeMaxDynamicSharedMemorySize, GEMM_SMEM);

    const int mb = (N + 127) / 128;
    const int nb = (N + SCAN_BLK - 1) / SCAN_BLK;

    // launch order engineered so launch #7 (incl. memset) = gemm3  → ncu profile
    cudaMemsetAsync(deg, 0, (size_t)N * sizeof(float));                          // 1
    deg_kernel<<<(E + 255) / 256, 256>>>(dst, deg, E);                           // 2
    split_kernel<<<(N * (D1 / 4) + 255) / 256, 256>>>(x, xhi, xlo, N * (D1 / 4));// 3
    wsplit_all<<<(49152 + 255) / 256, 256>>>(W1l, W1r, W2l, W2r, w);             // 4
    scan_part<<<nb, 256>>>(deg, bsum, N);                                        // 5
    scan_sums<<<1, 128>>>(bsum, boff, nb);                                       // 6
    gemm3<<<mb, 256, GEMM_SMEM>>>(xhi, xlo, w1l_hi, w1l_lo,                      // 7 ← profiled
                                  y1, D1, nullptr, y1 + 128, D1, nullptr, N);
    scan_write<<<nb, 256>>>(deg, boff, rowptr, cursor, N);                       // 8
    fill_csr<<<(E + 255) / 256, 256>>>(src, dst, cursor, csr, E);                // 9
    gemm3<<<mb, 256, GEMM_SMEM>>>(xhi, xlo, w1r_hi, w1r_lo,                      // 10
                                  z1, D1, b1, z1 + 128, D1, b1 + 128, N);

    int gw1 = 2 * N;  // warps
    gather1<<<(gw1 * 32 + 255) / 256, 256>>>(y1, z1, rowptr, csr, deg, hhi, hlo, N);

    gemm3<<<mb, 256, GEMM_SMEM>>>(hhi, hlo, w2_hi, w2_lo,
                                  y2, D2, nullptr, z2, D2, b2, N);

    gather2<<<(N * 32 + 255) / 256, 256>>>(y2, z2, rowptr, csr, deg, out, N);
}